// round 13
// baseline (speedup 1.0000x reference)
#include <cuda_runtime.h>
#include <cuda_fp16.h>
#include <math.h>
#include <stdint.h>

#define D_MODEL 512
#define N_HEAD  8
#define D_QKV   64
#define BB      4
#define SS      2048
#define ROWS    (BB*SS)   // 8192
#define MWORDS  (SS/32)   // 64 packed mask words per row

// Scratch (allocation-free rule: __device__ globals)
__device__ __align__(16) __half g_qn16 [ROWS*D_MODEL];
__device__ __align__(16) __half g_k16  [ROWS*D_MODEL];
__device__ __align__(16) __half g_v16  [ROWS*D_MODEL];
__device__ __align__(16) __half g_qh16 [ROWS*D_MODEL];
__device__ __align__(16) __half g_kh16 [ROWS*D_MODEL];
__device__ __align__(16) __half g_vh16 [ROWS*D_MODEL];
__device__ __align__(16) __half g_vt16 [ROWS*D_MODEL];      // V^T per (b,h): [b][h][d][s]
__device__ __align__(16) __half g_att16[ROWS*D_MODEL];
__device__ __align__(16) __half g_wt16 [4*D_MODEL*D_MODEL]; // transposed fp16 weights
__device__ uint32_t g_mpk[(size_t)BB*SS*MWORDS];            // bit-packed mask

// ---------------------------------------------------------------------------
// helpers
// ---------------------------------------------------------------------------
__device__ __forceinline__ uint32_t packh2(float a, float b) {
    __half2 h = __floats2half2_rn(a, b);
    return *(uint32_t*)&h;
}
__device__ __forceinline__ uint32_t h2exp2u(uint32_t x) {
    __half2 h = h2exp2(*(__half2*)&x);
    return *(uint32_t*)&h;
}
// fp16: D += A(16x16) * B(16x8), fp32 acc
__device__ __forceinline__ void mma16h(float* c, const uint32_t* a, const uint32_t* b) {
    asm volatile(
        "mma.sync.aligned.m16n8k16.row.col.f32.f16.f16.f32 "
        "{%0,%1,%2,%3},{%4,%5,%6,%7},{%8,%9},{%0,%1,%2,%3};"
        : "+f"(c[0]), "+f"(c[1]), "+f"(c[2]), "+f"(c[3])
        : "r"(a[0]), "r"(a[1]), "r"(a[2]), "r"(a[3]), "r"(b[0]), "r"(b[1]));
}
__device__ __forceinline__ void cpa16(uint32_t dst, const void* src) {
    asm volatile("cp.async.ca.shared.global [%0], [%1], 16;" :: "r"(dst), "l"(src));
}
__device__ __forceinline__ void cpa_commit() {
    asm volatile("cp.async.commit_group;");
}
template <int N>
__device__ __forceinline__ void cpa_wait() {
    asm volatile("cp.async.wait_group %0;" :: "n"(N));
}

// ---------------------------------------------------------------------------
// Fused prepass: one launch, blockIdx.x ranges select the job.
//   [0,1024)        weight transpose -> fp16 (4 weights x 256 tiles)
//   [1024,5120)     k/v fp32 -> fp16
//   [5120,6144)     LayerNorm(q) -> fp16
//   [6144,8192)     mask bit-pack (1 thread per output word, int4 loads)
// ---------------------------------------------------------------------------
__global__ void __launch_bounds__(256) prepass_kernel(
        const float* __restrict__ q, const float* __restrict__ k,
        const float* __restrict__ v, const int* __restrict__ mask,
        const float* __restrict__ w0, const float* __restrict__ w1,
        const float* __restrict__ w2, const float* __restrict__ w3,
        const float* __restrict__ gamma, const float* __restrict__ beta) {
    __shared__ float tile[32][33];
    const int bx = blockIdx.x;
    const int t = threadIdx.x;

    if (bx < 1024) {
        int z = bx >> 8, r = bx & 255;
        const float* src = (z == 0) ? w0 : (z == 1) ? w1 : (z == 2) ? w2 : w3;
        __half* d = g_wt16 + (size_t)z * D_MODEL * D_MODEL;
        int bxt = (r & 15) * 32, byt = (r >> 4) * 32;
        int tx = t & 31, ty = t >> 5;
#pragma unroll
        for (int i = 0; i < 32; i += 8)
            tile[ty + i][tx] = src[(size_t)(byt + ty + i) * D_MODEL + bxt + tx];
        __syncthreads();
#pragma unroll
        for (int i = 0; i < 32; i += 8)
            d[(size_t)(bxt + ty + i) * D_MODEL + byt + tx] = __float2half(tile[tx][ty + i]);
    } else if (bx < 5120) {
        int idx = bx - 1024;
        const float* src = (idx >> 11) ? v : k;
        __half* dst = (idx >> 11) ? g_v16 : g_k16;
        size_t i = ((size_t)(idx & 2047) * 256 + t) * 8;
        float4 a = *(const float4*)(src + i);
        float4 b = *(const float4*)(src + i + 4);
        uint4 o = make_uint4(packh2(a.x, a.y), packh2(a.z, a.w),
                             packh2(b.x, b.y), packh2(b.z, b.w));
        *(uint4*)(dst + i) = o;
    } else if (bx < 6144) {
        int row  = (bx - 5120) * 8 + (t >> 5);
        int lane = t & 31;
        const float4* xr = (const float4*)(q + (size_t)row * D_MODEL);
        float4 vv[4];
        float s = 0.f;
#pragma unroll
        for (int i = 0; i < 4; i++) {
            vv[i] = xr[lane + 32 * i];
            s += vv[i].x + vv[i].y + vv[i].z + vv[i].w;
        }
#pragma unroll
        for (int o = 16; o; o >>= 1) s += __shfl_xor_sync(0xffffffffu, s, o);
        float mu = s * (1.f / 512.f);
        float var = 0.f;
#pragma unroll
        for (int i = 0; i < 4; i++) {
            float a = vv[i].x - mu, b = vv[i].y - mu, c = vv[i].z - mu, d = vv[i].w - mu;
            var += a * a + b * b + c * c + d * d;
        }
#pragma unroll
        for (int o = 16; o; o >>= 1) var += __shfl_xor_sync(0xffffffffu, var, o);
        float rstd = rsqrtf(var * (1.f / 512.f) + 1e-6f);
        const float4* g4 = (const float4*)gamma;
        const float4* b4 = (const float4*)beta;
        __half* orow = g_qn16 + (size_t)row * D_MODEL;
#pragma unroll
        for (int i = 0; i < 4; i++) {
            float4 g = g4[lane + 32 * i], bb = b4[lane + 32 * i];
            uint2 o2 = make_uint2(packh2((vv[i].x - mu) * rstd * g.x + bb.x,
                                         (vv[i].y - mu) * rstd * g.y + bb.y),
                                  packh2((vv[i].z - mu) * rstd * g.z + bb.z,
                                         (vv[i].w - mu) * rstd * g.w + bb.w));
            *(uint2*)(orow + (lane + 32 * i) * 4) = o2;
        }
    } else {
        int base = bx - 6144;
        int row  = base * 4 + (t >> 6);
        int word = t & 63;
        const int4* mp = (const int4*)(mask + (size_t)row * SS + word * 32);
        uint32_t w = 0;
#pragma unroll
        for (int j = 0; j < 8; j++) {
            int4 m = mp[j];
            w |= (uint32_t)(m.x != 0) << (4 * j);
            w |= (uint32_t)(m.y != 0) << (4 * j + 1);
            w |= (uint32_t)(m.z != 0) << (4 * j + 2);
            w |= (uint32_t)(m.w != 0) << (4 * j + 3);
        }
        g_mpk[(size_t)row * MWORDS + word] = w;
    }
}

// ---------------------------------------------------------------------------
// V head transpose: vh16[b][s][h*64+d] -> vt[( (b*8+h)*64 + d )][s]
// ---------------------------------------------------------------------------
__global__ void transpose_v(const __half* __restrict__ vh, __half* __restrict__ vt) {
    __shared__ __align__(16) __half tile[64][72];
    int b = blockIdx.z, h = blockIdx.y, s0 = blockIdx.x * 64;
    int t = threadIdx.x;
#pragma unroll
    for (int i = 0; i < 2; i++) {
        int idx = t + 256 * i;
        int r = idx >> 3, c = idx & 7;
        *(uint4*)&tile[r][c * 8] =
            *(const uint4*)(vh + ((size_t)(b * SS + s0 + r)) * D_MODEL + h * 64 + c * 8);
    }
    __syncthreads();
#pragma unroll
    for (int i = 0; i < 8; i++) {
        int idx = t + 256 * i;
        int d = idx >> 5, sc = idx & 31;
        __half2 hp = make_half2(tile[2 * sc][d], tile[2 * sc + 1][d]);
        ((uint32_t*)(vt + (((size_t)(b * 8 + h) * 64 + d)) * SS + s0))[sc] = *(uint32_t*)&hp;
    }
}

// ---------------------------------------------------------------------------
// fp16 MMA GEMM body (unchanged from R12): tile 128x128, k-step 64.
// ---------------------------------------------------------------------------
#define HP2 36
#define HBUF2 (2*128*HP2)

template <bool RES, typename COUT>
__device__ __forceinline__ void gemm_body(const __half* __restrict__ A,
                                          const __half* __restrict__ Wt,
                                          COUT* __restrict__ C,
                                          const float* __restrict__ res,
                                          int m0, int n0) {
    extern __shared__ uint32_t sh[];
    const int t = threadIdx.x;
    const int warp = t >> 5, lane = t & 31, g = lane >> 2, tig = lane & 3;
    const int mw = warp >> 1, nw = warp & 1;

    auto stage = [&](int k0, int buf) {
        uint32_t* As = sh + buf * HBUF2;
        uint32_t* Bs = As + 128 * HP2;
        uint32_t as_base = (uint32_t)__cvta_generic_to_shared(As);
        uint32_t bs_base = (uint32_t)__cvta_generic_to_shared(Bs);
#pragma unroll
        for (int i = 0; i < 4; i++) {
            int idx = t + 256 * i;
            int r = idx >> 3, c = idx & 7;
            cpa16(as_base + (r * HP2 + c * 4) * 4, A + (size_t)(m0 + r) * 512 + k0 + c * 8);
        }
#pragma unroll
        for (int i = 0; i < 4; i++) {
            int idx = t + 256 * i;
            int r = idx >> 3, c = idx & 7;
            cpa16(bs_base + (r * HP2 + c * 4) * 4, Wt + (size_t)(n0 + r) * 512 + k0 + c * 8);
        }
        cpa_commit();
    };

    float acc[2][8][4] = {};

    stage(0, 0);
    for (int it = 0; it < 8; it++) {
        int buf = it & 1;
        cpa_wait<0>();
        __syncthreads();
        if (it + 1 < 8) stage((it + 1) * 64, buf ^ 1);

        const uint32_t* As = sh + buf * HBUF2;
        const uint32_t* Bs = As + 128 * HP2;
#pragma unroll
        for (int s = 0; s < 4; s++) {
            uint32_t a[2][4];
#pragma unroll
            for (int mt = 0; mt < 2; mt++) {
                int r = mw * 32 + mt * 16 + g;
                a[mt][0] = As[r * HP2 + s * 8 + tig];
                a[mt][1] = As[(r + 8) * HP2 + s * 8 + tig];
                a[mt][2] = As[r * HP2 + s * 8 + tig + 4];
                a[mt][3] = As[(r + 8) * HP2 + s * 8 + tig + 4];
            }
#pragma unroll
            for (int nt = 0; nt < 8; nt++) {
                int col = nw * 64 + nt * 8 + g;
                uint32_t b[2];
                b[0] = Bs[col * HP2 + s * 8 + tig];
                b[1] = Bs[col * HP2 + s * 8 + tig + 4];
                mma16h(acc[0][nt], a[0], b);
                mma16h(acc[1][nt], a[1], b);
            }
        }
    }
#pragma unroll
    for (int mt = 0; mt < 2; mt++) {
        int rbase = m0 + mw * 32 + mt * 16 + g;
#pragma unroll
        for (int nt = 0; nt < 8; nt++) {
            int col = n0 + nw * 64 + nt * 8 + 2 * tig;
            float2 v0 = make_float2(acc[mt][nt][0], acc[mt][nt][1]);
            float2 v1 = make_float2(acc[mt][nt][2], acc[mt][nt][3]);
            if (RES) {
                float2 r0 = *(const float2*)(res + (size_t)rbase * 512 + col);
                float2 r1 = *(const float2*)(res + (size_t)(rbase + 8) * 512 + col);
                v0.x += r0.x; v0.y += r0.y; v1.x += r1.x; v1.y += r1.y;
            }
            if (sizeof(COUT) == 4) {
                *(float2*)((float*)C + (size_t)rbase * 512 + col)       = v0;
                *(float2*)((float*)C + (size_t)(rbase + 8) * 512 + col) = v1;
            } else {
                *(uint32_t*)((__half*)C + (size_t)rbase * 512 + col)       = packh2(v0.x, v0.y);
                *(uint32_t*)((__half*)C + (size_t)(rbase + 8) * 512 + col) = packh2(v1.x, v1.y);
            }
        }
    }
}

__global__ void __launch_bounds__(256, 2) proj_kernel() {
    int z = blockIdx.z;
    const __half* A  = (z == 0) ? g_qn16 : (z == 1) ? g_k16 : g_v16;
    const __half* Wt = g_wt16 + (size_t)z * D_MODEL * D_MODEL;
    __half* C        = (z == 0) ? g_qh16 : (z == 1) ? g_kh16 : g_vh16;
    gemm_body<false, __half>(A, Wt, C, nullptr, blockIdx.y * 128, blockIdx.x * 128);
}

__global__ void __launch_bounds__(256, 2) fc_kernel(const float* __restrict__ res,
                                                    float* __restrict__ out) {
    gemm_body<true, float>(g_att16, g_wt16 + 3 * (size_t)D_MODEL * D_MODEL, out, res,
                           blockIdx.y * 128, blockIdx.x * 128);
}

// ---------------------------------------------------------------------------
// Flash attention, fp16 mma.sync. 256 thr, 128 q-rows/CTA, k-step 128
// (two 64-key halves per staged tile). Scale folded into Q (log2-domain
// scores); fp16x2 exp; mask via AND on packed p; l accumulated in fp32 from
// the same fp16 p as the PV numerator (consistent softmax ratio).
// ---------------------------------------------------------------------------
#define APK 36                             // K row pitch (64 halves + pad)
#define APV 68                             // V^T row pitch (128 halves + pad)
#define AKTILE (128*APK)                   // 4608 u32
#define AVTILE (64*APV)                    // 4352 u32
#define ABUF (AKTILE+AVTILE)               // 8960 u32 per buffer

__global__ void __launch_bounds__(256, 2) attn_fp16(const __half* __restrict__ qh,
                                                    const __half* __restrict__ kh,
                                                    const __half* __restrict__ vt,
                                                    const uint32_t* __restrict__ mpk,
                                                    __half* __restrict__ out) {
    extern __shared__ uint32_t sha[];

    const int q0 = blockIdx.x * 128;
    const int h  = blockIdx.y;
    const int b  = blockIdx.z;
    const int t = threadIdx.x, warp = t >> 5, lane = t & 31;
    const int g = lane >> 2, tig = lane & 3;

    const __half* qbase = qh + (size_t)b * SS * D_MODEL + h * D_QKV;
    const __half* kbase = kh + (size_t)b * SS * D_MODEL + h * D_QKV;
    const __half* vbase = vt + ((size_t)(b * 8 + h) * 64) * SS;   // [d][s]

    const int r0 = warp * 16 + g, r1 = r0 + 8;
    const uint32_t* pm0 = mpk + ((size_t)b * SS + q0 + r0) * MWORDS;
    const uint32_t* pm1 = mpk + ((size_t)b * SS + q0 + r1) * MWORDS;

    auto stage = [&](int k0, int buf) {
        uint32_t* Ks = sha + buf * ABUF;
        uint32_t* Vs = Ks + AKTILE;
        uint32_t ks_base = (uint32_t)__cvta_generic_to_shared(Ks);
        uint32_t vs_base = (uint32_t)__cvta_generic_to_shared(Vs);
#pragma unroll
        for (int i = 0; i < 4; i++) {      // K: 128 keys x 64 d (8 chunks/row)
            int idx = t + 256 * i;
            int r = idx >> 3, c = idx & 7;
            cpa16(ks_base + (r * APK + c * 4) * 4,
                  kbase + (size_t)(k0 + r) * D_MODEL + c * 8);
        }
#pragma unroll
        for (int i = 0; i < 4; i++) {      // V^T: 64 dout x 128 keys (16 chunks/row)
            int idx = t + 256 * i;
            int r = idx >> 4, c = idx & 15;
            cpa16(vs_base + (r * APV + c * 4) * 4,
                  vbase + (size_t)r * SS + k0 + c * 8);
        }
        cpa_commit();
    };

    // Q fragments, pre-scaled by log2(e)/8 so QK MMA emits log2-domain scores
    uint32_t qa[4][4];
    {
        const __half2 cexp2 = __float2half2_rn(0.125f * 1.44269504088896340736f);
        const uint32_t* q0p = (const uint32_t*)(qbase + (size_t)(q0 + r0) * D_MODEL);
        const uint32_t* q1p = (const uint32_t*)(qbase + (size_t)(q0 + r1) * D_MODEL);
#pragma unroll
        for (int c = 0; c < 4; c++) {
            __half2 a0 = __hmul2(*(__half2*)&q0p[8 * c + tig], cexp2);
            __half2 a1 = __hmul2(*(__half2*)&q1p[8 * c + tig], cexp2);
            __half2 a2 = __hmul2(*(__half2*)&q0p[8 * c + 4 + tig], cexp2);
            __half2 a3 = __hmul2(*(__half2*)&q1p[8 * c + 4 + tig], cexp2);
            qa[c][0] = *(uint32_t*)&a0; qa[c][1] = *(uint32_t*)&a1;
            qa[c][2] = *(uint32_t*)&a2; qa[c][3] = *(uint32_t*)&a3;
        }
    }

    float o[8][4] = {};
    float l0 = 0.f, l1 = 0.f;

    stage(0, 0);
    for (int it = 0; it < SS / 128; it++) {
        int buf = it & 1;
        int k0 = it * 128;
        uint4 wm0 = *(const uint4*)(pm0 + (k0 >> 5));
        uint4 wm1 = *(const uint4*)(pm1 + (k0 >> 5));
        cpa_wait<0>();
        __syncthreads();
        if (it + 1 < SS / 128) stage(k0 + 128, buf ^ 1);

        const uint32_t* Ks = sha + buf * ABUF;
        const uint32_t* Vs = Ks + AKTILE;

#pragma unroll
        for (int half = 0; half < 2; half++) {
            // S (log2-domain) = Qs @ K^T : 4 k-chunks x 8 n-tiles
            float sc[8][4] = {};
#pragma unroll
            for (int c = 0; c < 4; c++) {
#pragma unroll
                for (int nt = 0; nt < 8; nt++) {
                    const uint32_t* kr = &Ks[(half * 64 + nt * 8 + g) * APK + 8 * c + tig];
                    uint32_t bfr[2] = {kr[0], kr[4]};
                    mma16h(sc[nt], qa[c], bfr);
                }
            }

            uint32_t wa0 = half ? wm0.z : wm0.x, wa1 = half ? wm0.w : wm0.y;
            uint32_t wb0 = half ? wm1.z : wm1.x, wb1 = half ? wm1.w : wm1.y;

            // fp16x2 exp2, mask via AND, accumulate row sums in fp32 from the
            // same fp16 p used as PV A-fragments (consistent ratio).
            uint32_t pa[4][4];
#pragma unroll
            for (int nt = 0; nt < 8; nt++) {
                uint32_t wa = (nt < 4) ? wa0 : wa1;
                uint32_t wb = (nt < 4) ? wb0 : wb1;
                int bit = (nt & 3) * 8 + 2 * tig;
                uint32_t ta = wa >> bit, tb = wb >> bit;
                uint32_t ma = (ta & 1u) * 0xFFFFu + (ta & 2u) * 0x7FFF8000u;
                uint32_t mb = (tb & 1u) * 0xFFFFu + (tb & 2u) * 0x7FFF8000u;
                uint32_t p2a = h2exp2u(packh2(sc[nt][0], sc[nt][1])) & ma;
                uint32_t p2b = h2exp2u(packh2(sc[nt][2], sc[nt][3])) & mb;
                pa[nt >> 1][(nt & 1) * 2]     = p2a;
                pa[nt >> 1][(nt & 1) * 2 + 1] = p2b;
                float2 fa = __half22float2(*(__half2*)&p2a);
                float2 fb = __half22float2(*(__half2*)&p2b);
                l0 += fa.x + fa.y;
                l1 += fb.x + fb.y;
            }

            // O += P @ V
#pragma unroll
            for (int c = 0; c < 4; c++) {
#pragma unroll
                for (int nt = 0; nt < 8; nt++) {
                    const uint32_t* vr = &Vs[(nt * 8 + g) * APV + half * 32 + 8 * c + tig];
                    uint32_t bfr[2] = {vr[0], vr[4]};
                    mma16h(o[nt], pa[c], bfr);
                }
            }
        }
    }

    l0 += __shfl_xor_sync(0xffffffffu, l0, 1);
    l0 += __shfl_xor_sync(0xffffffffu, l0, 2);
    l1 += __shfl_xor_sync(0xffffffffu, l1, 1);
    l1 += __shfl_xor_sync(0xffffffffu, l1, 2);
    float il0 = 1.f / l0, il1 = 1.f / l1;
#pragma unroll
    for (int nt = 0; nt < 8; nt++) {
        int col = h * D_QKV + nt * 8 + 2 * tig;
        *(uint32_t*)(out + ((size_t)b * SS + q0 + r0) * D_MODEL + col) =
            packh2(o[nt][0] * il0, o[nt][1] * il0);
        *(uint32_t*)(out + ((size_t)b * SS + q0 + r1) * D_MODEL + col) =
            packh2(o[nt][2] * il1, o[nt][3] * il1);
    }
}

// ---------------------------------------------------------------------------
extern "C" void kernel_launch(void* const* d_in, const int* in_sizes, int n_in,
                              void* d_out, int out_size) {
    const float* q     = (const float*)d_in[0];
    const float* k     = (const float*)d_in[1];
    const float* v     = (const float*)d_in[2];
    const int*   mask  = (const int*)d_in[3];
    const float* Wq    = (const float*)d_in[4];
    const float* Wk    = (const float*)d_in[5];
    const float* Wv    = (const float*)d_in[6];
    const float* Wfc   = (const float*)d_in[7];
    const float* gamma = (const float*)d_in[8];
    const float* beta  = (const float*)d_in[9];
    float* out = (float*)d_out;

    __half *qh16, *kh16, *vh16, *vt16;
    uint32_t* mpk;
    cudaGetSymbolAddress((void**)&qh16,  g_qh16);
    cudaGetSymbolAddress((void**)&kh16,  g_kh16);
    cudaGetSymbolAddress((void**)&vh16,  g_vh16);
    cudaGetSymbolAddress((void**)&vt16,  g_vt16);
    __half* att16;
    cudaGetSymbolAddress((void**)&att16, g_att16);
    cudaGetSymbolAddress((void**)&mpk,   g_mpk);

    const int gemm_smem = 2 * HBUF2 * 4;       // 73728 B
    const int attn_smem = 2 * ABUF * 4;        // 71680 B
    cudaFuncSetAttribute(proj_kernel, cudaFuncAttributeMaxDynamicSharedMemorySize, gemm_smem);
    cudaFuncSetAttribute(fc_kernel,   cudaFuncAttributeMaxDynamicSharedMemorySize, gemm_smem);
    cudaFuncSetAttribute(attn_fp16,   cudaFuncAttributeMaxDynamicSharedMemorySize, attn_smem);

    // fused prepass: weight transpose, k/v cvt, LN, mask pack — one launch
    prepass_kernel<<<8192, 256>>>(q, k, v, mask, Wq, Wk, Wv, Wfc, gamma, beta);

    // fused Q/K/V projections (fp16 MMA, k-step 64)
    proj_kernel<<<dim3(D_MODEL / 128, ROWS / 128, 3), 256, gemm_smem>>>();

    // V head transpose for P@V B-fragments
    transpose_v<<<dim3(SS / 64, N_HEAD, BB), 256>>>(vh16, vt16);

    // flash attention (fp16 MMA, k-step 128, fp16x2 softmax)
    attn_fp16<<<dim3(SS / 128, N_HEAD, BB), 256, attn_smem>>>(qh16, kh16, vt16, mpk, att16);

    // FC + residual (fp16 MMA, fp32 out)
    fc_kernel<<<dim3(D_MODEL / 128, ROWS / 128), 256, gemm_smem>>>(q, out);
}

// round 14
// speedup vs baseline: 1.0674x; 1.0674x over previous
#include <cuda_runtime.h>
#include <cuda_fp16.h>
#include <math.h>
#include <stdint.h>

#define D_MODEL 512
#define N_HEAD  8
#define D_QKV   64
#define BB      4
#define SS      2048
#define ROWS    (BB*SS)   // 8192
#define MWORDS  (SS/32)   // 64 packed mask words per row

// Scratch (allocation-free rule: __device__ globals)
__device__ __align__(16) __half g_qn16 [ROWS*D_MODEL];
__device__ __align__(16) __half g_k16  [ROWS*D_MODEL];
__device__ __align__(16) __half g_v16  [ROWS*D_MODEL];
__device__ __align__(16) __half g_qh16 [ROWS*D_MODEL];
__device__ __align__(16) __half g_kh16 [ROWS*D_MODEL];
__device__ __align__(16) __half g_vh16 [ROWS*D_MODEL];
__device__ __align__(16) __half g_vt16 [ROWS*D_MODEL];      // V^T per (b,h): [b][h][d][s]
__device__ __align__(16) __half g_att16[ROWS*D_MODEL];
__device__ __align__(16) __half g_wt16 [4*D_MODEL*D_MODEL]; // transposed fp16 weights
__device__ uint32_t g_mpk[(size_t)BB*SS*MWORDS];            // bit-packed mask

// ---------------------------------------------------------------------------
// helpers
// ---------------------------------------------------------------------------
__device__ __forceinline__ float ex2f(float x) {
    float y;
    asm("ex2.approx.ftz.f32 %0, %1;" : "=f"(y) : "f"(x));
    return y;
}
__device__ __forceinline__ uint32_t packh2(float a, float b) {
    __half2 h = __floats2half2_rn(a, b);
    return *(uint32_t*)&h;
}
// fp16: D += A(16x16) * B(16x8), fp32 acc
__device__ __forceinline__ void mma16h(float* c, const uint32_t* a, const uint32_t* b) {
    asm volatile(
        "mma.sync.aligned.m16n8k16.row.col.f32.f16.f16.f32 "
        "{%0,%1,%2,%3},{%4,%5,%6,%7},{%8,%9},{%0,%1,%2,%3};"
        : "+f"(c[0]), "+f"(c[1]), "+f"(c[2]), "+f"(c[3])
        : "r"(a[0]), "r"(a[1]), "r"(a[2]), "r"(a[3]), "r"(b[0]), "r"(b[1]));
}
__device__ __forceinline__ void cpa16(uint32_t dst, const void* src) {
    asm volatile("cp.async.ca.shared.global [%0], [%1], 16;" :: "r"(dst), "l"(src));
}
__device__ __forceinline__ void cpa_commit() {
    asm volatile("cp.async.commit_group;");
}
template <int N>
__device__ __forceinline__ void cpa_wait() {
    asm volatile("cp.async.wait_group %0;" :: "n"(N));
}

// ---------------------------------------------------------------------------
// Fused prepass: one launch, blockIdx.x ranges select the job.
//   [0,1024)        weight transpose -> fp16 (4 weights x 256 tiles)
//   [1024,5120)     k/v fp32 -> fp16
//   [5120,6144)     LayerNorm(q) -> fp16
//   [6144,8192)     mask bit-pack (1 thread per output word, int4 loads)
// ---------------------------------------------------------------------------
__global__ void __launch_bounds__(256) prepass_kernel(
        const float* __restrict__ q, const float* __restrict__ k,
        const float* __restrict__ v, const int* __restrict__ mask,
        const float* __restrict__ w0, const float* __restrict__ w1,
        const float* __restrict__ w2, const float* __restrict__ w3,
        const float* __restrict__ gamma, const float* __restrict__ beta) {
    __shared__ float tile[32][33];
    const int bx = blockIdx.x;
    const int t = threadIdx.x;

    if (bx < 1024) {
        int z = bx >> 8, r = bx & 255;
        const float* src = (z == 0) ? w0 : (z == 1) ? w1 : (z == 2) ? w2 : w3;
        __half* d = g_wt16 + (size_t)z * D_MODEL * D_MODEL;
        int bxt = (r & 15) * 32, byt = (r >> 4) * 32;
        int tx = t & 31, ty = t >> 5;
#pragma unroll
        for (int i = 0; i < 32; i += 8)
            tile[ty + i][tx] = src[(size_t)(byt + ty + i) * D_MODEL + bxt + tx];
        __syncthreads();
#pragma unroll
        for (int i = 0; i < 32; i += 8)
            d[(size_t)(bxt + ty + i) * D_MODEL + byt + tx] = __float2half(tile[tx][ty + i]);
    } else if (bx < 5120) {
        int idx = bx - 1024;
        const float* src = (idx >> 11) ? v : k;
        __half* dst = (idx >> 11) ? g_v16 : g_k16;
        size_t i = ((size_t)(idx & 2047) * 256 + t) * 8;
        float4 a = *(const float4*)(src + i);
        float4 b = *(const float4*)(src + i + 4);
        uint4 o = make_uint4(packh2(a.x, a.y), packh2(a.z, a.w),
                             packh2(b.x, b.y), packh2(b.z, b.w));
        *(uint4*)(dst + i) = o;
    } else if (bx < 6144) {
        int row  = (bx - 5120) * 8 + (t >> 5);
        int lane = t & 31;
        const float4* xr = (const float4*)(q + (size_t)row * D_MODEL);
        float4 vv[4];
        float s = 0.f;
#pragma unroll
        for (int i = 0; i < 4; i++) {
            vv[i] = xr[lane + 32 * i];
            s += vv[i].x + vv[i].y + vv[i].z + vv[i].w;
        }
#pragma unroll
        for (int o = 16; o; o >>= 1) s += __shfl_xor_sync(0xffffffffu, s, o);
        float mu = s * (1.f / 512.f);
        float var = 0.f;
#pragma unroll
        for (int i = 0; i < 4; i++) {
            float a = vv[i].x - mu, b = vv[i].y - mu, c = vv[i].z - mu, d = vv[i].w - mu;
            var += a * a + b * b + c * c + d * d;
        }
#pragma unroll
        for (int o = 16; o; o >>= 1) var += __shfl_xor_sync(0xffffffffu, var, o);
        float rstd = rsqrtf(var * (1.f / 512.f) + 1e-6f);
        const float4* g4 = (const float4*)gamma;
        const float4* b4 = (const float4*)beta;
        __half* orow = g_qn16 + (size_t)row * D_MODEL;
#pragma unroll
        for (int i = 0; i < 4; i++) {
            float4 g = g4[lane + 32 * i], bb = b4[lane + 32 * i];
            uint2 o2 = make_uint2(packh2((vv[i].x - mu) * rstd * g.x + bb.x,
                                         (vv[i].y - mu) * rstd * g.y + bb.y),
                                  packh2((vv[i].z - mu) * rstd * g.z + bb.z,
                                         (vv[i].w - mu) * rstd * g.w + bb.w));
            *(uint2*)(orow + (lane + 32 * i) * 4) = o2;
        }
    } else {
        int base = bx - 6144;
        int row  = base * 4 + (t >> 6);
        int word = t & 63;
        const int4* mp = (const int4*)(mask + (size_t)row * SS + word * 32);
        uint32_t w = 0;
#pragma unroll
        for (int j = 0; j < 8; j++) {
            int4 m = mp[j];
            w |= (uint32_t)(m.x != 0) << (4 * j);
            w |= (uint32_t)(m.y != 0) << (4 * j + 1);
            w |= (uint32_t)(m.z != 0) << (4 * j + 2);
            w |= (uint32_t)(m.w != 0) << (4 * j + 3);
        }
        g_mpk[(size_t)row * MWORDS + word] = w;
    }
}

// ---------------------------------------------------------------------------
// V head transpose: vh16[b][s][h*64+d] -> vt[( (b*8+h)*64 + d )][s]
// ---------------------------------------------------------------------------
__global__ void transpose_v(const __half* __restrict__ vh, __half* __restrict__ vt) {
    __shared__ __align__(16) __half tile[64][72];
    int b = blockIdx.z, h = blockIdx.y, s0 = blockIdx.x * 64;
    int t = threadIdx.x;
#pragma unroll
    for (int i = 0; i < 2; i++) {
        int idx = t + 256 * i;
        int r = idx >> 3, c = idx & 7;
        *(uint4*)&tile[r][c * 8] =
            *(const uint4*)(vh + ((size_t)(b * SS + s0 + r)) * D_MODEL + h * 64 + c * 8);
    }
    __syncthreads();
#pragma unroll
    for (int i = 0; i < 8; i++) {
        int idx = t + 256 * i;
        int d = idx >> 5, sc = idx & 31;
        __half2 hp = make_half2(tile[2 * sc][d], tile[2 * sc + 1][d]);
        ((uint32_t*)(vt + (((size_t)(b * 8 + h) * 64 + d)) * SS + s0))[sc] = *(uint32_t*)&hp;
    }
}

// ---------------------------------------------------------------------------
// fp16 MMA GEMM body: tile 128x128, k-step 64, double-buffered cp.async.
// ---------------------------------------------------------------------------
#define HP2 36
#define HBUF2 (2*128*HP2)

template <bool RES, typename COUT>
__device__ __forceinline__ void gemm_body(const __half* __restrict__ A,
                                          const __half* __restrict__ Wt,
                                          COUT* __restrict__ C,
                                          const float* __restrict__ res,
                                          int m0, int n0) {
    extern __shared__ uint32_t sh[];
    const int t = threadIdx.x;
    const int warp = t >> 5, lane = t & 31, g = lane >> 2, tig = lane & 3;
    const int mw = warp >> 1, nw = warp & 1;

    auto stage = [&](int k0, int buf) {
        uint32_t* As = sh + buf * HBUF2;
        uint32_t* Bs = As + 128 * HP2;
        uint32_t as_base = (uint32_t)__cvta_generic_to_shared(As);
        uint32_t bs_base = (uint32_t)__cvta_generic_to_shared(Bs);
#pragma unroll
        for (int i = 0; i < 4; i++) {
            int idx = t + 256 * i;
            int r = idx >> 3, c = idx & 7;
            cpa16(as_base + (r * HP2 + c * 4) * 4, A + (size_t)(m0 + r) * 512 + k0 + c * 8);
        }
#pragma unroll
        for (int i = 0; i < 4; i++) {
            int idx = t + 256 * i;
            int r = idx >> 3, c = idx & 7;
            cpa16(bs_base + (r * HP2 + c * 4) * 4, Wt + (size_t)(n0 + r) * 512 + k0 + c * 8);
        }
        cpa_commit();
    };

    float acc[2][8][4] = {};

    stage(0, 0);
    for (int it = 0; it < 8; it++) {
        int buf = it & 1;
        cpa_wait<0>();
        __syncthreads();
        if (it + 1 < 8) stage((it + 1) * 64, buf ^ 1);

        const uint32_t* As = sh + buf * HBUF2;
        const uint32_t* Bs = As + 128 * HP2;
#pragma unroll
        for (int s = 0; s < 4; s++) {
            uint32_t a[2][4];
#pragma unroll
            for (int mt = 0; mt < 2; mt++) {
                int r = mw * 32 + mt * 16 + g;
                a[mt][0] = As[r * HP2 + s * 8 + tig];
                a[mt][1] = As[(r + 8) * HP2 + s * 8 + tig];
                a[mt][2] = As[r * HP2 + s * 8 + tig + 4];
                a[mt][3] = As[(r + 8) * HP2 + s * 8 + tig + 4];
            }
#pragma unroll
            for (int nt = 0; nt < 8; nt++) {
                int col = nw * 64 + nt * 8 + g;
                uint32_t b[2];
                b[0] = Bs[col * HP2 + s * 8 + tig];
                b[1] = Bs[col * HP2 + s * 8 + tig + 4];
                mma16h(acc[0][nt], a[0], b);
                mma16h(acc[1][nt], a[1], b);
            }
        }
    }
#pragma unroll
    for (int mt = 0; mt < 2; mt++) {
        int rbase = m0 + mw * 32 + mt * 16 + g;
#pragma unroll
        for (int nt = 0; nt < 8; nt++) {
            int col = n0 + nw * 64 + nt * 8 + 2 * tig;
            float2 v0 = make_float2(acc[mt][nt][0], acc[mt][nt][1]);
            float2 v1 = make_float2(acc[mt][nt][2], acc[mt][nt][3]);
            if (RES) {
                float2 r0 = *(const float2*)(res + (size_t)rbase * 512 + col);
                float2 r1 = *(const float2*)(res + (size_t)(rbase + 8) * 512 + col);
                v0.x += r0.x; v0.y += r0.y; v1.x += r1.x; v1.y += r1.y;
            }
            if (sizeof(COUT) == 4) {
                *(float2*)((float*)C + (size_t)rbase * 512 + col)       = v0;
                *(float2*)((float*)C + (size_t)(rbase + 8) * 512 + col) = v1;
            } else {
                *(uint32_t*)((__half*)C + (size_t)rbase * 512 + col)       = packh2(v0.x, v0.y);
                *(uint32_t*)((__half*)C + (size_t)(rbase + 8) * 512 + col) = packh2(v1.x, v1.y);
            }
        }
    }
}

__global__ void __launch_bounds__(256, 2) proj_kernel() {
    int z = blockIdx.z;
    const __half* A  = (z == 0) ? g_qn16 : (z == 1) ? g_k16 : g_v16;
    const __half* Wt = g_wt16 + (size_t)z * D_MODEL * D_MODEL;
    __half* C        = (z == 0) ? g_qh16 : (z == 1) ? g_kh16 : g_vh16;
    gemm_body<false, __half>(A, Wt, C, nullptr, blockIdx.y * 128, blockIdx.x * 128);
}

__global__ void __launch_bounds__(256, 2) fc_kernel(const float* __restrict__ res,
                                                    float* __restrict__ out) {
    gemm_body<true, float>(g_att16, g_wt16 + 3 * (size_t)D_MODEL * D_MODEL, out, res,
                           blockIdx.y * 128, blockIdx.x * 128);
}

// ---------------------------------------------------------------------------
// Flash attention, fp16 mma.sync (R12 structure: k-step 64, fp32 ex2,
// predicated mask select). Scale folded into Q -> log2-domain scores, so the
// softmax is a bare ex2 (no per-element FMUL).
// ---------------------------------------------------------------------------
#define AP 36                              // u32 pitch per 64-half row (+4 pad)
#define ATILE (64*AP)                      // one tile, u32 count
#define ABUF (2*ATILE)                     // K + V per buffer

__global__ void __launch_bounds__(256, 2) attn_fp16(const __half* __restrict__ qh,
                                                    const __half* __restrict__ kh,
                                                    const __half* __restrict__ vt,
                                                    const uint32_t* __restrict__ mpk,
                                                    __half* __restrict__ out) {
    extern __shared__ uint32_t sha[];

    const int q0 = blockIdx.x * 128;
    const int h  = blockIdx.y;
    const int b  = blockIdx.z;
    const int t = threadIdx.x, warp = t >> 5, lane = t & 31;
    const int g = lane >> 2, tig = lane & 3;

    const __half* qbase = qh + (size_t)b * SS * D_MODEL + h * D_QKV;
    const __half* kbase = kh + (size_t)b * SS * D_MODEL + h * D_QKV;
    const __half* vbase = vt + ((size_t)(b * 8 + h) * 64) * SS;   // [d][s]

    const int r0 = warp * 16 + g, r1 = r0 + 8;
    const uint32_t* pm0 = mpk + ((size_t)b * SS + q0 + r0) * MWORDS;
    const uint32_t* pm1 = mpk + ((size_t)b * SS + q0 + r1) * MWORDS;

    auto stage = [&](int k0, int buf) {
        uint32_t* Ks = sha + buf * ABUF;
        uint32_t* Vs = Ks + ATILE;
        uint32_t ks_base = (uint32_t)__cvta_generic_to_shared(Ks);
        uint32_t vs_base = (uint32_t)__cvta_generic_to_shared(Vs);
#pragma unroll
        for (int i = 0; i < 2; i++) {      // K: 64 keys x 64 d (8x16B chunks/row)
            int idx = t + 256 * i;
            int r = idx >> 3, c = idx & 7;
            cpa16(ks_base + (r * AP + c * 4) * 4,
                  kbase + (size_t)(k0 + r) * D_MODEL + c * 8);
        }
#pragma unroll
        for (int i = 0; i < 2; i++) {      // V^T: 64 dout x 64 keys
            int idx = t + 256 * i;
            int r = idx >> 3, c = idx & 7;
            cpa16(vs_base + (r * AP + c * 4) * 4,
                  vbase + (size_t)r * SS + k0 + c * 8);
        }
        cpa_commit();
    };

    // Q fragments, pre-scaled by log2(e)/8 -> QK MMA emits log2-domain scores
    uint32_t qa[4][4];
    {
        const __half2 cexp2 = __float2half2_rn(0.125f * 1.44269504088896340736f);
        const uint32_t* q0p = (const uint32_t*)(qbase + (size_t)(q0 + r0) * D_MODEL);
        const uint32_t* q1p = (const uint32_t*)(qbase + (size_t)(q0 + r1) * D_MODEL);
#pragma unroll
        for (int c = 0; c < 4; c++) {
            __half2 a0 = __hmul2(*(__half2*)&q0p[8 * c + tig], cexp2);
            __half2 a1 = __hmul2(*(__half2*)&q1p[8 * c + tig], cexp2);
            __half2 a2 = __hmul2(*(__half2*)&q0p[8 * c + 4 + tig], cexp2);
            __half2 a3 = __hmul2(*(__half2*)&q1p[8 * c + 4 + tig], cexp2);
            qa[c][0] = *(uint32_t*)&a0; qa[c][1] = *(uint32_t*)&a1;
            qa[c][2] = *(uint32_t*)&a2; qa[c][3] = *(uint32_t*)&a3;
        }
    }

    float o[8][4] = {};
    float l0 = 0.f, l1 = 0.f;

    stage(0, 0);
    for (int it = 0; it < SS / 64; it++) {
        int buf = it & 1;
        int k0 = it * 64;
        uint2 wm0 = *(const uint2*)(pm0 + (k0 >> 5));
        uint2 wm1 = *(const uint2*)(pm1 + (k0 >> 5));
        cpa_wait<0>();
        __syncthreads();
        if (it + 1 < SS / 64) stage(k0 + 64, buf ^ 1);

        const uint32_t* Ks = sha + buf * ABUF;
        const uint32_t* Vs = Ks + ATILE;

        // S (log2-domain) = Qs @ K^T : 4 k-chunks x 8 n-tiles
        float sc[8][4] = {};
#pragma unroll
        for (int c = 0; c < 4; c++) {
#pragma unroll
            for (int nt = 0; nt < 8; nt++) {
                const uint32_t* kr = &Ks[(nt * 8 + g) * AP + 8 * c + tig];
                uint32_t bfr[2] = {kr[0], kr[4]};
                mma16h(sc[nt], qa[c], bfr);
            }
        }

        // masked exp2 (max-free), accumulate row sums, pack P to fp16 A-frags
        uint32_t pa[4][4];
#pragma unroll
        for (int nt = 0; nt < 8; nt++) {
            uint32_t wa = (nt < 4) ? wm0.x : wm0.y;
            uint32_t wb = (nt < 4) ? wm1.x : wm1.y;
            int bit = (nt & 3) * 8 + 2 * tig;
            float p0 = ((wa >> bit)       & 1u) ? ex2f(sc[nt][0]) : 0.f;
            float p1 = ((wa >> (bit + 1)) & 1u) ? ex2f(sc[nt][1]) : 0.f;
            float p2 = ((wb >> bit)       & 1u) ? ex2f(sc[nt][2]) : 0.f;
            float p3 = ((wb >> (bit + 1)) & 1u) ? ex2f(sc[nt][3]) : 0.f;
            l0 += p0 + p1; l1 += p2 + p3;
            pa[nt >> 1][(nt & 1) * 2]     = packh2(p0, p1);
            pa[nt >> 1][(nt & 1) * 2 + 1] = packh2(p2, p3);
        }

        // O += P @ V : 4 k-chunks (16 keys each) x 8 dout-tiles
#pragma unroll
        for (int c = 0; c < 4; c++) {
#pragma unroll
            for (int nt = 0; nt < 8; nt++) {
                const uint32_t* vr = &Vs[(nt * 8 + g) * AP + 8 * c + tig];
                uint32_t bfr[2] = {vr[0], vr[4]};
                mma16h(o[nt], pa[c], bfr);
            }
        }
    }

    l0 += __shfl_xor_sync(0xffffffffu, l0, 1);
    l0 += __shfl_xor_sync(0xffffffffu, l0, 2);
    l1 += __shfl_xor_sync(0xffffffffu, l1, 1);
    l1 += __shfl_xor_sync(0xffffffffu, l1, 2);
    float il0 = 1.f / l0, il1 = 1.f / l1;
#pragma unroll
    for (int nt = 0; nt < 8; nt++) {
        int col = h * D_QKV + nt * 8 + 2 * tig;
        *(uint32_t*)(out + ((size_t)b * SS + q0 + r0) * D_MODEL + col) =
            packh2(o[nt][0] * il0, o[nt][1] * il0);
        *(uint32_t*)(out + ((size_t)b * SS + q0 + r1) * D_MODEL + col) =
            packh2(o[nt][2] * il1, o[nt][3] * il1);
    }
}

// ---------------------------------------------------------------------------
extern "C" void kernel_launch(void* const* d_in, const int* in_sizes, int n_in,
                              void* d_out, int out_size) {
    const float* q     = (const float*)d_in[0];
    const float* k     = (const float*)d_in[1];
    const float* v     = (const float*)d_in[2];
    const int*   mask  = (const int*)d_in[3];
    const float* Wq    = (const float*)d_in[4];
    const float* Wk    = (const float*)d_in[5];
    const float* Wv    = (const float*)d_in[6];
    const float* Wfc   = (const float*)d_in[7];
    const float* gamma = (const float*)d_in[8];
    const float* beta  = (const float*)d_in[9];
    float* out = (float*)d_out;

    __half *qh16, *kh16, *vh16, *vt16, *att16;
    uint32_t* mpk;
    cudaGetSymbolAddress((void**)&qh16,  g_qh16);
    cudaGetSymbolAddress((void**)&kh16,  g_kh16);
    cudaGetSymbolAddress((void**)&vh16,  g_vh16);
    cudaGetSymbolAddress((void**)&vt16,  g_vt16);
    cudaGetSymbolAddress((void**)&att16, g_att16);
    cudaGetSymbolAddress((void**)&mpk,   g_mpk);

    const int gemm_smem = 2 * HBUF2 * 4;       // 73728 B
    const int attn_smem = 2 * ABUF * 4;        // 36864 B
    cudaFuncSetAttribute(proj_kernel, cudaFuncAttributeMaxDynamicSharedMemorySize, gemm_smem);
    cudaFuncSetAttribute(fc_kernel,   cudaFuncAttributeMaxDynamicSharedMemorySize, gemm_smem);
    cudaFuncSetAttribute(attn_fp16,   cudaFuncAttributeMaxDynamicSharedMemorySize, attn_smem);

    // fused prepass: weight transpose, k/v cvt, LN, mask pack — one launch
    prepass_kernel<<<8192, 256>>>(q, k, v, mask, Wq, Wk, Wv, Wfc, gamma, beta);

    // fused Q/K/V projections (fp16 MMA, k-step 64)
    proj_kernel<<<dim3(D_MODEL / 128, ROWS / 128, 3), 256, gemm_smem>>>();

    // V head transpose for P@V B-fragments
    transpose_v<<<dim3(SS / 64, N_HEAD, BB), 256>>>(vh16, vt16);

    // flash attention (fp16 MMA, log2-domain softmax, bit-packed mask)
    attn_fp16<<<dim3(SS / 128, N_HEAD, BB), 256, attn_smem>>>(qh16, kh16, vt16, mpk, att16);

    // FC + residual (fp16 MMA, fp32 out)
    fc_kernel<<<dim3(D_MODEL / 128, ROWS / 128), 256, gemm_smem>>>(q, out);
}

// round 15
// speedup vs baseline: 1.1014x; 1.0319x over previous
#include <cuda_runtime.h>
#include <cuda_fp16.h>
#include <math.h>
#include <stdint.h>

#define D_MODEL 512
#define N_HEAD  8
#define D_QKV   64
#define BB      4
#define SS      2048
#define ROWS    (BB*SS)   // 8192
#define MWORDS  (SS/32)   // 64 packed mask words per row

// Scratch (allocation-free rule: __device__ globals)
__device__ __align__(16) __half g_qn16 [ROWS*D_MODEL];
__device__ __align__(16) __half g_k16  [ROWS*D_MODEL];
__device__ __align__(16) __half g_v16  [ROWS*D_MODEL];
__device__ __align__(16) __half g_qh16 [ROWS*D_MODEL];
__device__ __align__(16) __half g_kh16 [ROWS*D_MODEL];
__device__ __align__(16) __half g_vt16 [ROWS*D_MODEL];      // V^T per (b,h): [b][h][d][s]
__device__ __align__(16) __half g_att16[ROWS*D_MODEL];
__device__ __align__(16) __half g_wt16 [4*D_MODEL*D_MODEL]; // transposed fp16 weights
__device__ uint32_t g_mpk[(size_t)BB*SS*MWORDS];            // bit-packed mask

// ---------------------------------------------------------------------------
// helpers
// ---------------------------------------------------------------------------
__device__ __forceinline__ float ex2f(float x) {
    float y;
    asm("ex2.approx.ftz.f32 %0, %1;" : "=f"(y) : "f"(x));
    return y;
}
__device__ __forceinline__ uint32_t packh2(float a, float b) {
    __half2 h = __floats2half2_rn(a, b);
    return *(uint32_t*)&h;
}
// fp16: D += A(16x16) * B(16x8), fp32 acc
__device__ __forceinline__ void mma16h(float* c, const uint32_t* a, const uint32_t* b) {
    asm volatile(
        "mma.sync.aligned.m16n8k16.row.col.f32.f16.f16.f32 "
        "{%0,%1,%2,%3},{%4,%5,%6,%7},{%8,%9},{%0,%1,%2,%3};"
        : "+f"(c[0]), "+f"(c[1]), "+f"(c[2]), "+f"(c[3])
        : "r"(a[0]), "r"(a[1]), "r"(a[2]), "r"(a[3]), "r"(b[0]), "r"(b[1]));
}
__device__ __forceinline__ void cpa16(uint32_t dst, const void* src) {
    asm volatile("cp.async.ca.shared.global [%0], [%1], 16;" :: "r"(dst), "l"(src));
}
__device__ __forceinline__ void cpa_commit() {
    asm volatile("cp.async.commit_group;");
}
template <int N>
__device__ __forceinline__ void cpa_wait() {
    asm volatile("cp.async.wait_group %0;" :: "n"(N));
}

// ---------------------------------------------------------------------------
// Fused prepass: one launch, blockIdx.x ranges select the job.
// ---------------------------------------------------------------------------
__global__ void __launch_bounds__(256) prepass_kernel(
        const float* __restrict__ q, const float* __restrict__ k,
        const float* __restrict__ v, const int* __restrict__ mask,
        const float* __restrict__ w0, const float* __restrict__ w1,
        const float* __restrict__ w2, const float* __restrict__ w3,
        const float* __restrict__ gamma, const float* __restrict__ beta) {
    __shared__ float tile[32][33];
    const int bx = blockIdx.x;
    const int t = threadIdx.x;

    if (bx < 1024) {
        int z = bx >> 8, r = bx & 255;
        const float* src = (z == 0) ? w0 : (z == 1) ? w1 : (z == 2) ? w2 : w3;
        __half* d = g_wt16 + (size_t)z * D_MODEL * D_MODEL;
        int bxt = (r & 15) * 32, byt = (r >> 4) * 32;
        int tx = t & 31, ty = t >> 5;
#pragma unroll
        for (int i = 0; i < 32; i += 8)
            tile[ty + i][tx] = src[(size_t)(byt + ty + i) * D_MODEL + bxt + tx];
        __syncthreads();
#pragma unroll
        for (int i = 0; i < 32; i += 8)
            d[(size_t)(bxt + ty + i) * D_MODEL + byt + tx] = __float2half(tile[tx][ty + i]);
    } else if (bx < 5120) {
        int idx = bx - 1024;
        const float* src = (idx >> 11) ? v : k;
        __half* dst = (idx >> 11) ? g_v16 : g_k16;
        size_t i = ((size_t)(idx & 2047) * 256 + t) * 8;
        float4 a = *(const float4*)(src + i);
        float4 b = *(const float4*)(src + i + 4);
        uint4 o = make_uint4(packh2(a.x, a.y), packh2(a.z, a.w),
                             packh2(b.x, b.y), packh2(b.z, b.w));
        *(uint4*)(dst + i) = o;
    } else if (bx < 6144) {
        int row  = (bx - 5120) * 8 + (t >> 5);
        int lane = t & 31;
        const float4* xr = (const float4*)(q + (size_t)row * D_MODEL);
        float4 vv[4];
        float s = 0.f;
#pragma unroll
        for (int i = 0; i < 4; i++) {
            vv[i] = xr[lane + 32 * i];
            s += vv[i].x + vv[i].y + vv[i].z + vv[i].w;
        }
#pragma unroll
        for (int o = 16; o; o >>= 1) s += __shfl_xor_sync(0xffffffffu, s, o);
        float mu = s * (1.f / 512.f);
        float var = 0.f;
#pragma unroll
        for (int i = 0; i < 4; i++) {
            float a = vv[i].x - mu, b = vv[i].y - mu, c = vv[i].z - mu, d = vv[i].w - mu;
            var += a * a + b * b + c * c + d * d;
        }
#pragma unroll
        for (int o = 16; o; o >>= 1) var += __shfl_xor_sync(0xffffffffu, var, o);
        float rstd = rsqrtf(var * (1.f / 512.f) + 1e-6f);
        const float4* g4 = (const float4*)gamma;
        const float4* b4 = (const float4*)beta;
        __half* orow = g_qn16 + (size_t)row * D_MODEL;
#pragma unroll
        for (int i = 0; i < 4; i++) {
            float4 g = g4[lane + 32 * i], bb = b4[lane + 32 * i];
            uint2 o2 = make_uint2(packh2((vv[i].x - mu) * rstd * g.x + bb.x,
                                         (vv[i].y - mu) * rstd * g.y + bb.y),
                                  packh2((vv[i].z - mu) * rstd * g.z + bb.z,
                                         (vv[i].w - mu) * rstd * g.w + bb.w));
            *(uint2*)(orow + (lane + 32 * i) * 4) = o2;
        }
    } else {
        int base = bx - 6144;
        int row  = base * 4 + (t >> 6);
        int word = t & 63;
        const int4* mp = (const int4*)(mask + (size_t)row * SS + word * 32);
        uint32_t w = 0;
#pragma unroll
        for (int j = 0; j < 8; j++) {
            int4 m = mp[j];
            w |= (uint32_t)(m.x != 0) << (4 * j);
            w |= (uint32_t)(m.y != 0) << (4 * j + 1);
            w |= (uint32_t)(m.z != 0) << (4 * j + 2);
            w |= (uint32_t)(m.w != 0) << (4 * j + 3);
        }
        g_mpk[(size_t)row * MWORDS + word] = w;
    }
}

// ---------------------------------------------------------------------------
// fp16 MMA GEMM body: tile 128x128, k-step 64, THREE-stage cp.async pipeline.
// MODE: 0 = half out, 1 = float out + residual, 2 = V^T transposed out (via
// smem transpose, writes g_vt16 directly).
// ---------------------------------------------------------------------------
#define HP2 36
#define HBUF2 (2*128*HP2)                  // one stage (A+B), u32 count

template <int MODE, typename COUT>
__device__ __forceinline__ void gemm_body(const __half* __restrict__ A,
                                          const __half* __restrict__ Wt,
                                          COUT* __restrict__ C,
                                          const float* __restrict__ res,
                                          int m0, int n0) {
    extern __shared__ uint32_t sh[];
    const int t = threadIdx.x;
    const int warp = t >> 5, lane = t & 31, g = lane >> 2, tig = lane & 3;
    const int mw = warp >> 1, nw = warp & 1;

    auto stage = [&](int k0, int buf) {
        uint32_t* As = sh + buf * HBUF2;
        uint32_t* Bs = As + 128 * HP2;
        uint32_t as_base = (uint32_t)__cvta_generic_to_shared(As);
        uint32_t bs_base = (uint32_t)__cvta_generic_to_shared(Bs);
#pragma unroll
        for (int i = 0; i < 4; i++) {
            int idx = t + 256 * i;
            int r = idx >> 3, c = idx & 7;
            cpa16(as_base + (r * HP2 + c * 4) * 4, A + (size_t)(m0 + r) * 512 + k0 + c * 8);
        }
#pragma unroll
        for (int i = 0; i < 4; i++) {
            int idx = t + 256 * i;
            int r = idx >> 3, c = idx & 7;
            cpa16(bs_base + (r * HP2 + c * 4) * 4, Wt + (size_t)(n0 + r) * 512 + k0 + c * 8);
        }
        cpa_commit();
    };

    float acc[2][8][4] = {};

    stage(0, 0);
    stage(64, 1);
    int buf = 0;
    for (int it = 0; it < 8; it++) {
        if (it < 6) cpa_wait<1>(); else cpa_wait<0>();
        __syncthreads();
        if (it + 2 < 8) stage((it + 2) * 64, (it + 2) % 3);

        const uint32_t* As = sh + buf * HBUF2;
        const uint32_t* Bs = As + 128 * HP2;
#pragma unroll
        for (int s = 0; s < 4; s++) {
            uint32_t a[2][4];
#pragma unroll
            for (int mt = 0; mt < 2; mt++) {
                int r = mw * 32 + mt * 16 + g;
                a[mt][0] = As[r * HP2 + s * 8 + tig];
                a[mt][1] = As[(r + 8) * HP2 + s * 8 + tig];
                a[mt][2] = As[r * HP2 + s * 8 + tig + 4];
                a[mt][3] = As[(r + 8) * HP2 + s * 8 + tig + 4];
            }
#pragma unroll
            for (int nt = 0; nt < 8; nt++) {
                int col = nw * 64 + nt * 8 + g;
                uint32_t b[2];
                b[0] = Bs[col * HP2 + s * 8 + tig];
                b[1] = Bs[col * HP2 + s * 8 + tig + 4];
                mma16h(acc[0][nt], a[0], b);
                mma16h(acc[1][nt], a[1], b);
            }
        }
        buf = (buf == 2) ? 0 : buf + 1;
    }

    if (MODE == 2) {
        // transposed epilogue -> g_vt16, via smem [128 rows][132 cols] halves
        __syncthreads();                    // all warps done with stage buffers
        __half* smt = (__half*)sh;
#pragma unroll
        for (int mt = 0; mt < 2; mt++) {
            int r = mw * 32 + mt * 16 + g;
#pragma unroll
            for (int nt = 0; nt < 8; nt++) {
                int c = nw * 64 + nt * 8 + 2 * tig;
                *(uint32_t*)&smt[r * 132 + c]       = packh2(acc[mt][nt][0], acc[mt][nt][1]);
                *(uint32_t*)&smt[(r + 8) * 132 + c] = packh2(acc[mt][nt][2], acc[mt][nt][3]);
            }
        }
        __syncthreads();
        const int b = m0 >> 11;
        const int s0 = m0 & 2047;
        __half* vtb = g_vt16 + ((size_t)b * 512 + n0) * SS + s0;
#pragma unroll
        for (int i = 0; i < 8; i++) {
            int idx = t + 256 * i;
            int dp = idx >> 4, sc4 = idx & 15;
            __half tmp[8];
#pragma unroll
            for (int j = 0; j < 8; j++) tmp[j] = smt[(sc4 * 8 + j) * 132 + dp];
            *(uint4*)(vtb + (size_t)dp * SS + sc4 * 8) = *(const uint4*)tmp;
        }
        return;
    }

#pragma unroll
    for (int mt = 0; mt < 2; mt++) {
        int rbase = m0 + mw * 32 + mt * 16 + g;
#pragma unroll
        for (int nt = 0; nt < 8; nt++) {
            int col = n0 + nw * 64 + nt * 8 + 2 * tig;
            float2 v0 = make_float2(acc[mt][nt][0], acc[mt][nt][1]);
            float2 v1 = make_float2(acc[mt][nt][2], acc[mt][nt][3]);
            if (MODE == 1) {
                float2 r0 = *(const float2*)(res + (size_t)rbase * 512 + col);
                float2 r1 = *(const float2*)(res + (size_t)(rbase + 8) * 512 + col);
                v0.x += r0.x; v0.y += r0.y; v1.x += r1.x; v1.y += r1.y;
                *(float2*)((float*)C + (size_t)rbase * 512 + col)       = v0;
                *(float2*)((float*)C + (size_t)(rbase + 8) * 512 + col) = v1;
            } else {
                *(uint32_t*)((__half*)C + (size_t)rbase * 512 + col)       = packh2(v0.x, v0.y);
                *(uint32_t*)((__half*)C + (size_t)(rbase + 8) * 512 + col) = packh2(v1.x, v1.y);
            }
        }
    }
}

// Fused Q/K/V projection: grid.z picks operand set; V writes V^T directly.
__global__ void __launch_bounds__(256, 2) proj_kernel() {
    int z = blockIdx.z;
    int m0 = blockIdx.y * 128, n0 = blockIdx.x * 128;
    if (z == 0)
        gemm_body<0, __half>(g_qn16, g_wt16, g_qh16, nullptr, m0, n0);
    else if (z == 1)
        gemm_body<0, __half>(g_k16, g_wt16 + (size_t)D_MODEL * D_MODEL, g_kh16,
                             nullptr, m0, n0);
    else
        gemm_body<2, __half>(g_v16, g_wt16 + 2 * (size_t)D_MODEL * D_MODEL, g_vt16,
                             nullptr, m0, n0);
}

// FC + residual
__global__ void __launch_bounds__(256, 2) fc_kernel(const float* __restrict__ res,
                                                    float* __restrict__ out) {
    gemm_body<1, float>(g_att16, g_wt16 + 3 * (size_t)D_MODEL * D_MODEL, out, res,
                        blockIdx.y * 128, blockIdx.x * 128);
}

// ---------------------------------------------------------------------------
// Flash attention, fp16 mma.sync. 128 thr (4 warps), 128 q-rows/CTA, 32
// q-rows per warp (2 m-tiles sharing every K/V B-fragment read -> LDS bytes
// halved). k-step 64, log2-domain softmax (scale folded into Q), bit-packed
// mask, P register-resident.
// ---------------------------------------------------------------------------
#define AP 36                              // u32 pitch per 64-half row (+4 pad)
#define ATILE (64*AP)                      // one tile, u32 count
#define ABUF (2*ATILE)                     // K + V per buffer

__global__ void __launch_bounds__(128, 2) attn_fp16(const __half* __restrict__ qh,
                                                    const __half* __restrict__ kh,
                                                    const __half* __restrict__ vt,
                                                    const uint32_t* __restrict__ mpk,
                                                    __half* __restrict__ out) {
    extern __shared__ uint32_t sha[];

    const int q0 = blockIdx.x * 128;
    const int h  = blockIdx.y;
    const int b  = blockIdx.z;
    const int t = threadIdx.x, warp = t >> 5, lane = t & 31;
    const int g = lane >> 2, tig = lane & 3;

    const __half* qbase = qh + (size_t)b * SS * D_MODEL + h * D_QKV;
    const __half* kbase = kh + (size_t)b * SS * D_MODEL + h * D_QKV;
    const __half* vbase = vt + ((size_t)(b * 8 + h) * 64) * SS;   // [d][s]

    const int rw = warp * 32 + g;          // warp's base row (+ q0)
    const uint32_t* pm[4];
#pragma unroll
    for (int j = 0; j < 4; j++)
        pm[j] = mpk + ((size_t)b * SS + q0 + rw + 8 * j) * MWORDS;

    auto stage = [&](int k0, int buf) {
        uint32_t* Ks = sha + buf * ABUF;
        uint32_t* Vs = Ks + ATILE;
        uint32_t ks_base = (uint32_t)__cvta_generic_to_shared(Ks);
        uint32_t vs_base = (uint32_t)__cvta_generic_to_shared(Vs);
#pragma unroll
        for (int i = 0; i < 4; i++) {      // K: 64 keys x 64 d (8x16B chunks/row)
            int idx = t + 128 * i;
            int r = idx >> 3, c = idx & 7;
            cpa16(ks_base + (r * AP + c * 4) * 4,
                  kbase + (size_t)(k0 + r) * D_MODEL + c * 8);
        }
#pragma unroll
        for (int i = 0; i < 4; i++) {      // V^T: 64 dout x 64 keys
            int idx = t + 128 * i;
            int r = idx >> 3, c = idx & 7;
            cpa16(vs_base + (r * AP + c * 4) * 4,
                  vbase + (size_t)r * SS + k0 + c * 8);
        }
        cpa_commit();
    };

    // Q fragments for both m-tiles, pre-scaled by log2(e)/8
    uint32_t qa[2][4][4];
    {
        const __half2 cexp2 = __float2half2_rn(0.125f * 1.44269504088896340736f);
#pragma unroll
        for (int mt = 0; mt < 2; mt++) {
            const uint32_t* q0p =
                (const uint32_t*)(qbase + (size_t)(q0 + rw + mt * 16) * D_MODEL);
            const uint32_t* q1p =
                (const uint32_t*)(qbase + (size_t)(q0 + rw + mt * 16 + 8) * D_MODEL);
#pragma unroll
            for (int c = 0; c < 4; c++) {
                __half2 a0 = __hmul2(*(__half2*)&q0p[8 * c + tig], cexp2);
                __half2 a1 = __hmul2(*(__half2*)&q1p[8 * c + tig], cexp2);
                __half2 a2 = __hmul2(*(__half2*)&q0p[8 * c + 4 + tig], cexp2);
                __half2 a3 = __hmul2(*(__half2*)&q1p[8 * c + 4 + tig], cexp2);
                qa[mt][c][0] = *(uint32_t*)&a0; qa[mt][c][1] = *(uint32_t*)&a1;
                qa[mt][c][2] = *(uint32_t*)&a2; qa[mt][c][3] = *(uint32_t*)&a3;
            }
        }
    }

    float o[2][8][4] = {};
    float l[4] = {0.f, 0.f, 0.f, 0.f};     // [mt*2 + (row g:0 / g+8:1)]

    stage(0, 0);
    for (int it = 0; it < SS / 64; it++) {
        int buf = it & 1;
        int k0 = it * 64;
        uint2 wm[4];
#pragma unroll
        for (int j = 0; j < 4; j++) wm[j] = *(const uint2*)(pm[j] + (k0 >> 5));
        cpa_wait<0>();
        __syncthreads();
        if (it + 1 < SS / 64) stage(k0 + 64, buf ^ 1);

        const uint32_t* Ks = sha + buf * ABUF;
        const uint32_t* Vs = Ks + ATILE;

        // S (log2-domain), both m-tiles sharing each K fragment read
        float sc[2][8][4] = {};
#pragma unroll
        for (int c = 0; c < 4; c++) {
#pragma unroll
            for (int nt = 0; nt < 8; nt++) {
                const uint32_t* kr = &Ks[(nt * 8 + g) * AP + 8 * c + tig];
                uint32_t bfr[2] = {kr[0], kr[4]};
                mma16h(sc[0][nt], qa[0][c], bfr);
                mma16h(sc[1][nt], qa[1][c], bfr);
            }
        }

        // masked exp2 (max-free), row sums, pack P to fp16 A-frags
        uint32_t pa[2][4][4];
#pragma unroll
        for (int mt = 0; mt < 2; mt++) {
#pragma unroll
            for (int nt = 0; nt < 8; nt++) {
                uint32_t wa = (nt < 4) ? wm[2 * mt].x : wm[2 * mt].y;
                uint32_t wb = (nt < 4) ? wm[2 * mt + 1].x : wm[2 * mt + 1].y;
                int bit = (nt & 3) * 8 + 2 * tig;
                float p0 = ((wa >> bit)       & 1u) ? ex2f(sc[mt][nt][0]) : 0.f;
                float p1 = ((wa >> (bit + 1)) & 1u) ? ex2f(sc[mt][nt][1]) : 0.f;
                float p2 = ((wb >> bit)       & 1u) ? ex2f(sc[mt][nt][2]) : 0.f;
                float p3 = ((wb >> (bit + 1)) & 1u) ? ex2f(sc[mt][nt][3]) : 0.f;
                l[2 * mt]     += p0 + p1;
                l[2 * mt + 1] += p2 + p3;
                pa[mt][nt >> 1][(nt & 1) * 2]     = packh2(p0, p1);
                pa[mt][nt >> 1][(nt & 1) * 2 + 1] = packh2(p2, p3);
            }
        }

        // O += P @ V, both m-tiles sharing each V fragment read
#pragma unroll
        for (int c = 0; c < 4; c++) {
#pragma unroll
            for (int nt = 0; nt < 8; nt++) {
                const uint32_t* vr = &Vs[(nt * 8 + g) * AP + 8 * c + tig];
                uint32_t bfr[2] = {vr[0], vr[4]};
                mma16h(o[0][nt], pa[0][c], bfr);
                mma16h(o[1][nt], pa[1][c], bfr);
            }
        }
    }

#pragma unroll
    for (int j = 0; j < 4; j++) {
        l[j] += __shfl_xor_sync(0xffffffffu, l[j], 1);
        l[j] += __shfl_xor_sync(0xffffffffu, l[j], 2);
    }
#pragma unroll
    for (int mt = 0; mt < 2; mt++) {
        float il0 = 1.f / l[2 * mt], il1 = 1.f / l[2 * mt + 1];
        int row0 = q0 + rw + mt * 16;
#pragma unroll
        for (int nt = 0; nt < 8; nt++) {
            int col = h * D_QKV + nt * 8 + 2 * tig;
            *(uint32_t*)(out + ((size_t)b * SS + row0) * D_MODEL + col) =
                packh2(o[mt][nt][0] * il0, o[mt][nt][1] * il0);
            *(uint32_t*)(out + ((size_t)b * SS + row0 + 8) * D_MODEL + col) =
                packh2(o[mt][nt][2] * il1, o[mt][nt][3] * il1);
        }
    }
}

// ---------------------------------------------------------------------------
extern "C" void kernel_launch(void* const* d_in, const int* in_sizes, int n_in,
                              void* d_out, int out_size) {
    const float* q     = (const float*)d_in[0];
    const float* k     = (const float*)d_in[1];
    const float* v     = (const float*)d_in[2];
    const int*   mask  = (const int*)d_in[3];
    const float* Wq    = (const float*)d_in[4];
    const float* Wk    = (const float*)d_in[5];
    const float* Wv    = (const float*)d_in[6];
    const float* Wfc   = (const float*)d_in[7];
    const float* gamma = (const float*)d_in[8];
    const float* beta  = (const float*)d_in[9];
    float* out = (float*)d_out;

    __half *qh16, *kh16, *vt16, *att16;
    uint32_t* mpk;
    cudaGetSymbolAddress((void**)&qh16,  g_qh16);
    cudaGetSymbolAddress((void**)&kh16,  g_kh16);
    cudaGetSymbolAddress((void**)&vt16,  g_vt16);
    cudaGetSymbolAddress((void**)&att16, g_att16);
    cudaGetSymbolAddress((void**)&mpk,   g_mpk);

    const int gemm_smem = 3 * HBUF2 * 4;       // 110592 B (3-stage)
    const int attn_smem = 2 * ABUF * 4;        // 36864 B
    cudaFuncSetAttribute(proj_kernel, cudaFuncAttributeMaxDynamicSharedMemorySize, gemm_smem);
    cudaFuncSetAttribute(fc_kernel,   cudaFuncAttributeMaxDynamicSharedMemorySize, gemm_smem);
    cudaFuncSetAttribute(attn_fp16,   cudaFuncAttributeMaxDynamicSharedMemorySize, attn_smem);

    // fused prepass: weight transpose, k/v cvt, LN, mask pack — one launch
    prepass_kernel<<<8192, 256>>>(q, k, v, mask, Wq, Wk, Wv, Wfc, gamma, beta);

    // fused Q/K/V projections (fp16 MMA, 3-stage); V writes V^T directly
    proj_kernel<<<dim3(D_MODEL / 128, ROWS / 128, 3), 256, gemm_smem>>>();

    // flash attention (fp16 MMA, 32 q-rows/warp, log2-domain softmax)
    attn_fp16<<<dim3(SS / 128, N_HEAD, BB), 128, attn_smem>>>(qh16, kh16, vt16, mpk, att16);

    // FC + residual (fp16 MMA, fp32 out)
    fc_kernel<<<dim3(D_MODEL / 128, ROWS / 128), 256, gemm_smem>>>(q, out);
}

// round 16
// speedup vs baseline: 1.1393x; 1.0344x over previous
#include <cuda_runtime.h>
#include <cuda_fp16.h>
#include <math.h>
#include <stdint.h>

#define D_MODEL 512
#define N_HEAD  8
#define D_QKV   64
#define BB      4
#define SS      2048
#define ROWS    (BB*SS)   // 8192
#define MWORDS  (SS/32)   // 64 packed mask words per row

// Scratch (allocation-free rule: __device__ globals)
__device__ __align__(16) __half g_qn16 [ROWS*D_MODEL];
__device__ __align__(16) __half g_k16  [ROWS*D_MODEL];
__device__ __align__(16) __half g_v16  [ROWS*D_MODEL];
__device__ __align__(16) __half g_qh16 [ROWS*D_MODEL];
__device__ __align__(16) __half g_kh16 [ROWS*D_MODEL];
__device__ __align__(16) __half g_vt16 [ROWS*D_MODEL];      // V^T per (b,h): [b][h][d][s]
__device__ __align__(16) __half g_att16[ROWS*D_MODEL];
__device__ __align__(16) __half g_wt16 [4*D_MODEL*D_MODEL]; // transposed fp16 weights
__device__ uint32_t g_mpk[(size_t)BB*SS*MWORDS];            // bit-packed mask

// ---------------------------------------------------------------------------
// helpers
// ---------------------------------------------------------------------------
__device__ __forceinline__ float ex2f(float x) {
    float y;
    asm("ex2.approx.ftz.f32 %0, %1;" : "=f"(y) : "f"(x));
    return y;
}
__device__ __forceinline__ uint32_t packh2(float a, float b) {
    __half2 h = __floats2half2_rn(a, b);
    return *(uint32_t*)&h;
}
// fp16: D += A(16x16) * B(16x8), fp32 acc
__device__ __forceinline__ void mma16h(float* c, const uint32_t* a, const uint32_t* b) {
    asm volatile(
        "mma.sync.aligned.m16n8k16.row.col.f32.f16.f16.f32 "
        "{%0,%1,%2,%3},{%4,%5,%6,%7},{%8,%9},{%0,%1,%2,%3};"
        : "+f"(c[0]), "+f"(c[1]), "+f"(c[2]), "+f"(c[3])
        : "r"(a[0]), "r"(a[1]), "r"(a[2]), "r"(a[3]), "r"(b[0]), "r"(b[1]));
}
__device__ __forceinline__ void ldsm4(uint32_t* d, uint32_t addr) {
    asm volatile(
        "ldmatrix.sync.aligned.m8n8.x4.shared.b16 {%0,%1,%2,%3}, [%4];"
        : "=r"(d[0]), "=r"(d[1]), "=r"(d[2]), "=r"(d[3]) : "r"(addr));
}
__device__ __forceinline__ void cpa16(uint32_t dst, const void* src) {
    asm volatile("cp.async.ca.shared.global [%0], [%1], 16;" :: "r"(dst), "l"(src));
}
__device__ __forceinline__ void cpa_commit() {
    asm volatile("cp.async.commit_group;");
}
template <int N>
__device__ __forceinline__ void cpa_wait() {
    asm volatile("cp.async.wait_group %0;" :: "n"(N));
}

// ---------------------------------------------------------------------------
// Fused prepass: one launch, blockIdx.x ranges select the job.
// ---------------------------------------------------------------------------
__global__ void __launch_bounds__(256) prepass_kernel(
        const float* __restrict__ q, const float* __restrict__ k,
        const float* __restrict__ v, const int* __restrict__ mask,
        const float* __restrict__ w0, const float* __restrict__ w1,
        const float* __restrict__ w2, const float* __restrict__ w3,
        const float* __restrict__ gamma, const float* __restrict__ beta) {
    __shared__ float tile[32][33];
    const int bx = blockIdx.x;
    const int t = threadIdx.x;

    if (bx < 1024) {
        int z = bx >> 8, r = bx & 255;
        const float* src = (z == 0) ? w0 : (z == 1) ? w1 : (z == 2) ? w2 : w3;
        __half* d = g_wt16 + (size_t)z * D_MODEL * D_MODEL;
        int bxt = (r & 15) * 32, byt = (r >> 4) * 32;
        int tx = t & 31, ty = t >> 5;
#pragma unroll
        for (int i = 0; i < 32; i += 8)
            tile[ty + i][tx] = src[(size_t)(byt + ty + i) * D_MODEL + bxt + tx];
        __syncthreads();
#pragma unroll
        for (int i = 0; i < 32; i += 8)
            d[(size_t)(bxt + ty + i) * D_MODEL + byt + tx] = __float2half(tile[tx][ty + i]);
    } else if (bx < 5120) {
        int idx = bx - 1024;
        const float* src = (idx >> 11) ? v : k;
        __half* dst = (idx >> 11) ? g_v16 : g_k16;
        size_t i = ((size_t)(idx & 2047) * 256 + t) * 8;
        float4 a = *(const float4*)(src + i);
        float4 b = *(const float4*)(src + i + 4);
        uint4 o = make_uint4(packh2(a.x, a.y), packh2(a.z, a.w),
                             packh2(b.x, b.y), packh2(b.z, b.w));
        *(uint4*)(dst + i) = o;
    } else if (bx < 6144) {
        int row  = (bx - 5120) * 8 + (t >> 5);
        int lane = t & 31;
        const float4* xr = (const float4*)(q + (size_t)row * D_MODEL);
        float4 vv[4];
        float s = 0.f;
#pragma unroll
        for (int i = 0; i < 4; i++) {
            vv[i] = xr[lane + 32 * i];
            s += vv[i].x + vv[i].y + vv[i].z + vv[i].w;
        }
#pragma unroll
        for (int o = 16; o; o >>= 1) s += __shfl_xor_sync(0xffffffffu, s, o);
        float mu = s * (1.f / 512.f);
        float var = 0.f;
#pragma unroll
        for (int i = 0; i < 4; i++) {
            float a = vv[i].x - mu, b = vv[i].y - mu, c = vv[i].z - mu, d = vv[i].w - mu;
            var += a * a + b * b + c * c + d * d;
        }
#pragma unroll
        for (int o = 16; o; o >>= 1) var += __shfl_xor_sync(0xffffffffu, var, o);
        float rstd = rsqrtf(var * (1.f / 512.f) + 1e-6f);
        const float4* g4 = (const float4*)gamma;
        const float4* b4 = (const float4*)beta;
        __half* orow = g_qn16 + (size_t)row * D_MODEL;
#pragma unroll
        for (int i = 0; i < 4; i++) {
            float4 g = g4[lane + 32 * i], bb = b4[lane + 32 * i];
            uint2 o2 = make_uint2(packh2((vv[i].x - mu) * rstd * g.x + bb.x,
                                         (vv[i].y - mu) * rstd * g.y + bb.y),
                                  packh2((vv[i].z - mu) * rstd * g.z + bb.z,
                                         (vv[i].w - mu) * rstd * g.w + bb.w));
            *(uint2*)(orow + (lane + 32 * i) * 4) = o2;
        }
    } else {
        int base = bx - 6144;
        int row  = base * 4 + (t >> 6);
        int word = t & 63;
        const int4* mp = (const int4*)(mask + (size_t)row * SS + word * 32);
        uint32_t w = 0;
#pragma unroll
        for (int j = 0; j < 8; j++) {
            int4 m = mp[j];
            w |= (uint32_t)(m.x != 0) << (4 * j);
            w |= (uint32_t)(m.y != 0) << (4 * j + 1);
            w |= (uint32_t)(m.z != 0) << (4 * j + 2);
            w |= (uint32_t)(m.w != 0) << (4 * j + 3);
        }
        g_mpk[(size_t)row * MWORDS + word] = w;
    }
}

// ---------------------------------------------------------------------------
// fp16 MMA GEMM body: tile 128x128, k-step 64, 3-stage cp.async, ldmatrix
// fragment loads. MODE: 0 = half out, 1 = float out + residual,
// 2 = V^T transposed out (smem transpose, writes g_vt16).
// ---------------------------------------------------------------------------
#define HP2 36
#define HBUF2 (2*128*HP2)                  // one stage (A+B), u32 count

template <int MODE, typename COUT>
__device__ __forceinline__ void gemm_body(const __half* __restrict__ A,
                                          const __half* __restrict__ Wt,
                                          COUT* __restrict__ C,
                                          const float* __restrict__ res,
                                          int m0, int n0) {
    extern __shared__ uint32_t sh[];
    const int t = threadIdx.x;
    const int warp = t >> 5, lane = t & 31, g = lane >> 2, tig = lane & 3;
    const int mw = warp >> 1, nw = warp & 1;
    const int lm = lane >> 3, lj = lane & 7;     // ldmatrix: matrix id, row

    const uint32_t sh_base = (uint32_t)__cvta_generic_to_shared(sh);

    // ldmatrix byte offsets within a stage (s=0)
    uint32_t a_off[2], b_off[4];
#pragma unroll
    for (int mt = 0; mt < 2; mt++)
        a_off[mt] = ((mw * 32 + mt * 16 + (lm & 1) * 8 + lj) * HP2 + (lm >> 1) * 4) * 4;
#pragma unroll
    for (int p = 0; p < 4; p++)
        b_off[p] = ((128 + nw * 64 + p * 16 + (lm >> 1) * 8 + lj) * HP2 + (lm & 1) * 4) * 4;

    auto stage = [&](int k0, int buf) {
        uint32_t base = sh_base + buf * HBUF2 * 4;
#pragma unroll
        for (int i = 0; i < 4; i++) {
            int idx = t + 256 * i;
            int r = idx >> 3, c = idx & 7;
            cpa16(base + (r * HP2 + c * 4) * 4, A + (size_t)(m0 + r) * 512 + k0 + c * 8);
        }
#pragma unroll
        for (int i = 0; i < 4; i++) {
            int idx = t + 256 * i;
            int r = idx >> 3, c = idx & 7;
            cpa16(base + ((128 + r) * HP2 + c * 4) * 4,
                  Wt + (size_t)(n0 + r) * 512 + k0 + c * 8);
        }
        cpa_commit();
    };

    float acc[2][8][4] = {};

    stage(0, 0);
    stage(64, 1);
    int buf = 0;
    for (int it = 0; it < 8; it++) {
        if (it < 7) cpa_wait<1>(); else cpa_wait<0>();
        __syncthreads();
        if (it + 2 < 8) stage((it + 2) * 64, (it + 2) % 3);

        uint32_t sbase = sh_base + buf * HBUF2 * 4;
#pragma unroll
        for (int s = 0; s < 4; s++) {
            uint32_t a[2][4];
            ldsm4(a[0], sbase + a_off[0] + s * 32);
            ldsm4(a[1], sbase + a_off[1] + s * 32);
#pragma unroll
            for (int p = 0; p < 4; p++) {
                uint32_t bq[4];
                ldsm4(bq, sbase + b_off[p] + s * 32);
                mma16h(acc[0][2 * p],     a[0], bq);
                mma16h(acc[1][2 * p],     a[1], bq);
                mma16h(acc[0][2 * p + 1], a[0], bq + 2);
                mma16h(acc[1][2 * p + 1], a[1], bq + 2);
            }
        }
        buf = (buf == 2) ? 0 : buf + 1;
    }

    if (MODE == 2) {
        // transposed epilogue -> g_vt16, via smem [128 rows][132 cols] halves
        __syncthreads();                    // all warps done with stage buffers
        __half* smt = (__half*)sh;
#pragma unroll
        for (int mt = 0; mt < 2; mt++) {
            int r = mw * 32 + mt * 16 + g;
#pragma unroll
            for (int nt = 0; nt < 8; nt++) {
                int c = nw * 64 + nt * 8 + 2 * tig;
                *(uint32_t*)&smt[r * 132 + c]       = packh2(acc[mt][nt][0], acc[mt][nt][1]);
                *(uint32_t*)&smt[(r + 8) * 132 + c] = packh2(acc[mt][nt][2], acc[mt][nt][3]);
            }
        }
        __syncthreads();
        const int b = m0 >> 11;
        const int s0 = m0 & 2047;
        __half* vtb = g_vt16 + ((size_t)b * 512 + n0) * SS + s0;
#pragma unroll
        for (int i = 0; i < 8; i++) {
            int idx = t + 256 * i;
            int dp = idx >> 4, sc4 = idx & 15;
            __half tmp[8];
#pragma unroll
            for (int j = 0; j < 8; j++) tmp[j] = smt[(sc4 * 8 + j) * 132 + dp];
            *(uint4*)(vtb + (size_t)dp * SS + sc4 * 8) = *(const uint4*)tmp;
        }
        return;
    }

#pragma unroll
    for (int mt = 0; mt < 2; mt++) {
        int rbase = m0 + mw * 32 + mt * 16 + g;
#pragma unroll
        for (int nt = 0; nt < 8; nt++) {
            int col = n0 + nw * 64 + nt * 8 + 2 * tig;
            float2 v0 = make_float2(acc[mt][nt][0], acc[mt][nt][1]);
            float2 v1 = make_float2(acc[mt][nt][2], acc[mt][nt][3]);
            if (MODE == 1) {
                float2 r0 = *(const float2*)(res + (size_t)rbase * 512 + col);
                float2 r1 = *(const float2*)(res + (size_t)(rbase + 8) * 512 + col);
                v0.x += r0.x; v0.y += r0.y; v1.x += r1.x; v1.y += r1.y;
                *(float2*)((float*)C + (size_t)rbase * 512 + col)       = v0;
                *(float2*)((float*)C + (size_t)(rbase + 8) * 512 + col) = v1;
            } else {
                *(uint32_t*)((__half*)C + (size_t)rbase * 512 + col)       = packh2(v0.x, v0.y);
                *(uint32_t*)((__half*)C + (size_t)(rbase + 8) * 512 + col) = packh2(v1.x, v1.y);
            }
        }
    }
}

// Fused Q/K/V projection: grid.z picks operand set; V writes V^T directly.
__global__ void __launch_bounds__(256, 2) proj_kernel() {
    int z = blockIdx.z;
    int m0 = blockIdx.y * 128, n0 = blockIdx.x * 128;
    if (z == 0)
        gemm_body<0, __half>(g_qn16, g_wt16, g_qh16, nullptr, m0, n0);
    else if (z == 1)
        gemm_body<0, __half>(g_k16, g_wt16 + (size_t)D_MODEL * D_MODEL, g_kh16,
                             nullptr, m0, n0);
    else
        gemm_body<2, __half>(g_v16, g_wt16 + 2 * (size_t)D_MODEL * D_MODEL, g_vt16,
                             nullptr, m0, n0);
}

// FC + residual
__global__ void __launch_bounds__(256, 2) fc_kernel(const float* __restrict__ res,
                                                    float* __restrict__ out) {
    gemm_body<1, float>(g_att16, g_wt16 + 3 * (size_t)D_MODEL * D_MODEL, out, res,
                        blockIdx.y * 128, blockIdx.x * 128);
}

// ---------------------------------------------------------------------------
// Flash attention, fp16 mma.sync (unchanged from R15): 128 thr (4 warps),
// 128 q-rows/CTA, 32 q-rows/warp (B-fragments shared across m-tiles),
// k-step 64, log2-domain softmax, bit-packed mask.
// ---------------------------------------------------------------------------
#define AP 36                              // u32 pitch per 64-half row (+4 pad)
#define ATILE (64*AP)                      // one tile, u32 count
#define ABUF (2*ATILE)                     // K + V per buffer

__global__ void __launch_bounds__(128, 2) attn_fp16(const __half* __restrict__ qh,
                                                    const __half* __restrict__ kh,
                                                    const __half* __restrict__ vt,
                                                    const uint32_t* __restrict__ mpk,
                                                    __half* __restrict__ out) {
    extern __shared__ uint32_t sha[];

    const int q0 = blockIdx.x * 128;
    const int h  = blockIdx.y;
    const int b  = blockIdx.z;
    const int t = threadIdx.x, warp = t >> 5, lane = t & 31;
    const int g = lane >> 2, tig = lane & 3;

    const __half* qbase = qh + (size_t)b * SS * D_MODEL + h * D_QKV;
    const __half* kbase = kh + (size_t)b * SS * D_MODEL + h * D_QKV;
    const __half* vbase = vt + ((size_t)(b * 8 + h) * 64) * SS;   // [d][s]

    const int rw = warp * 32 + g;          // warp's base row (+ q0)
    const uint32_t* pm[4];
#pragma unroll
    for (int j = 0; j < 4; j++)
        pm[j] = mpk + ((size_t)b * SS + q0 + rw + 8 * j) * MWORDS;

    auto stage = [&](int k0, int buf) {
        uint32_t* Ks = sha + buf * ABUF;
        uint32_t* Vs = Ks + ATILE;
        uint32_t ks_base = (uint32_t)__cvta_generic_to_shared(Ks);
        uint32_t vs_base = (uint32_t)__cvta_generic_to_shared(Vs);
#pragma unroll
        for (int i = 0; i < 4; i++) {      // K: 64 keys x 64 d (8x16B chunks/row)
            int idx = t + 128 * i;
            int r = idx >> 3, c = idx & 7;
            cpa16(ks_base + (r * AP + c * 4) * 4,
                  kbase + (size_t)(k0 + r) * D_MODEL + c * 8);
        }
#pragma unroll
        for (int i = 0; i < 4; i++) {      // V^T: 64 dout x 64 keys
            int idx = t + 128 * i;
            int r = idx >> 3, c = idx & 7;
            cpa16(vs_base + (r * AP + c * 4) * 4,
                  vbase + (size_t)r * SS + k0 + c * 8);
        }
        cpa_commit();
    };

    // Q fragments for both m-tiles, pre-scaled by log2(e)/8
    uint32_t qa[2][4][4];
    {
        const __half2 cexp2 = __float2half2_rn(0.125f * 1.44269504088896340736f);
#pragma unroll
        for (int mt = 0; mt < 2; mt++) {
            const uint32_t* q0p =
                (const uint32_t*)(qbase + (size_t)(q0 + rw + mt * 16) * D_MODEL);
            const uint32_t* q1p =
                (const uint32_t*)(qbase + (size_t)(q0 + rw + mt * 16 + 8) * D_MODEL);
#pragma unroll
            for (int c = 0; c < 4; c++) {
                __half2 a0 = __hmul2(*(__half2*)&q0p[8 * c + tig], cexp2);
                __half2 a1 = __hmul2(*(__half2*)&q1p[8 * c + tig], cexp2);
                __half2 a2 = __hmul2(*(__half2*)&q0p[8 * c + 4 + tig], cexp2);
                __half2 a3 = __hmul2(*(__half2*)&q1p[8 * c + 4 + tig], cexp2);
                qa[mt][c][0] = *(uint32_t*)&a0; qa[mt][c][1] = *(uint32_t*)&a1;
                qa[mt][c][2] = *(uint32_t*)&a2; qa[mt][c][3] = *(uint32_t*)&a3;
            }
        }
    }

    float o[2][8][4] = {};
    float l[4] = {0.f, 0.f, 0.f, 0.f};     // [mt*2 + (row g:0 / g+8:1)]

    stage(0, 0);
    for (int it = 0; it < SS / 64; it++) {
        int buf = it & 1;
        int k0 = it * 64;
        uint2 wm[4];
#pragma unroll
        for (int j = 0; j < 4; j++) wm[j] = *(const uint2*)(pm[j] + (k0 >> 5));
        cpa_wait<0>();
        __syncthreads();
        if (it + 1 < SS / 64) stage(k0 + 64, buf ^ 1);

        const uint32_t* Ks = sha + buf * ABUF;
        const uint32_t* Vs = Ks + ATILE;

        // S (log2-domain), both m-tiles sharing each K fragment read
        float sc[2][8][4] = {};
#pragma unroll
        for (int c = 0; c < 4; c++) {
#pragma unroll
            for (int nt = 0; nt < 8; nt++) {
                const uint32_t* kr = &Ks[(nt * 8 + g) * AP + 8 * c + tig];
                uint32_t bfr[2] = {kr[0], kr[4]};
                mma16h(sc[0][nt], qa[0][c], bfr);
                mma16h(sc[1][nt], qa[1][c], bfr);
            }
        }

        // masked exp2 (max-free), row sums, pack P to fp16 A-frags
        uint32_t pa[2][4][4];
#pragma unroll
        for (int mt = 0; mt < 2; mt++) {
#pragma unroll
            for (int nt = 0; nt < 8; nt++) {
                uint32_t wa = (nt < 4) ? wm[2 * mt].x : wm[2 * mt].y;
                uint32_t wb = (nt < 4) ? wm[2 * mt + 1].x : wm[2 * mt + 1].y;
                int bit = (nt & 3) * 8 + 2 * tig;
                float p0 = ((wa >> bit)       & 1u) ? ex2f(sc[mt][nt][0]) : 0.f;
                float p1 = ((wa >> (bit + 1)) & 1u) ? ex2f(sc[mt][nt][1]) : 0.f;
                float p2 = ((wb >> bit)       & 1u) ? ex2f(sc[mt][nt][2]) : 0.f;
                float p3 = ((wb >> (bit + 1)) & 1u) ? ex2f(sc[mt][nt][3]) : 0.f;
                l[2 * mt]     += p0 + p1;
                l[2 * mt + 1] += p2 + p3;
                pa[mt][nt >> 1][(nt & 1) * 2]     = packh2(p0, p1);
                pa[mt][nt >> 1][(nt & 1) * 2 + 1] = packh2(p2, p3);
            }
        }

        // O += P @ V, both m-tiles sharing each V fragment read
#pragma unroll
        for (int c = 0; c < 4; c++) {
#pragma unroll
            for (int nt = 0; nt < 8; nt++) {
                const uint32_t* vr = &Vs[(nt * 8 + g) * AP + 8 * c + tig];
                uint32_t bfr[2] = {vr[0], vr[4]};
                mma16h(o[0][nt], pa[0][c], bfr);
                mma16h(o[1][nt], pa[1][c], bfr);
            }
        }
    }

#pragma unroll
    for (int j = 0; j < 4; j++) {
        l[j] += __shfl_xor_sync(0xffffffffu, l[j], 1);
        l[j] += __shfl_xor_sync(0xffffffffu, l[j], 2);
    }
#pragma unroll
    for (int mt = 0; mt < 2; mt++) {
        float il0 = 1.f / l[2 * mt], il1 = 1.f / l[2 * mt + 1];
        int row0 = q0 + rw + mt * 16;
#pragma unroll
        for (int nt = 0; nt < 8; nt++) {
            int col = h * D_QKV + nt * 8 + 2 * tig;
            *(uint32_t*)(out + ((size_t)b * SS + row0) * D_MODEL + col) =
                packh2(o[mt][nt][0] * il0, o[mt][nt][1] * il0);
            *(uint32_t*)(out + ((size_t)b * SS + row0 + 8) * D_MODEL + col) =
                packh2(o[mt][nt][2] * il1, o[mt][nt][3] * il1);
        }
    }
}

// ---------------------------------------------------------------------------
extern "C" void kernel_launch(void* const* d_in, const int* in_sizes, int n_in,
                              void* d_out, int out_size) {
    const float* q     = (const float*)d_in[0];
    const float* k     = (const float*)d_in[1];
    const float* v     = (const float*)d_in[2];
    const int*   mask  = (const int*)d_in[3];
    const float* Wq    = (const float*)d_in[4];
    const float* Wk    = (const float*)d_in[5];
    const float* Wv    = (const float*)d_in[6];
    const float* Wfc   = (const float*)d_in[7];
    const float* gamma = (const float*)d_in[8];
    const float* beta  = (const float*)d_in[9];
    float* out = (float*)d_out;

    __half *qh16, *kh16, *vt16, *att16;
    uint32_t* mpk;
    cudaGetSymbolAddress((void**)&qh16,  g_qh16);
    cudaGetSymbolAddress((void**)&kh16,  g_kh16);
    cudaGetSymbolAddress((void**)&vt16,  g_vt16);
    cudaGetSymbolAddress((void**)&att16, g_att16);
    cudaGetSymbolAddress((void**)&mpk,   g_mpk);

    const int gemm_smem = 3 * HBUF2 * 4;       // 110592 B (3-stage)
    const int attn_smem = 2 * ABUF * 4;        // 36864 B
    cudaFuncSetAttribute(proj_kernel, cudaFuncAttributeMaxDynamicSharedMemorySize, gemm_smem);
    cudaFuncSetAttribute(fc_kernel,   cudaFuncAttributeMaxDynamicSharedMemorySize, gemm_smem);
    cudaFuncSetAttribute(attn_fp16,   cudaFuncAttributeMaxDynamicSharedMemorySize, attn_smem);

    // fused prepass: weight transpose, k/v cvt, LN, mask pack — one launch
    prepass_kernel<<<8192, 256>>>(q, k, v, mask, Wq, Wk, Wv, Wfc, gamma, beta);

    // fused Q/K/V projections (fp16 MMA, 3-stage, ldmatrix); V writes V^T
    proj_kernel<<<dim3(D_MODEL / 128, ROWS / 128, 3), 256, gemm_smem>>>();

    // flash attention (fp16 MMA, 32 q-rows/warp, log2-domain softmax)
    attn_fp16<<<dim3(SS / 128, N_HEAD, BB), 128, attn_smem>>>(qh16, kh16, vt16, mpk, att16);

    // FC + residual (fp16 MMA, fp32 out)
    fc_kernel<<<dim3(D_MODEL / 128, ROWS / 128), 256, gemm_smem>>>(q, out);
}